// round 16
// baseline (speedup 1.0000x reference)
#include <cuda_runtime.h>
#include <cuda_bf16.h>
#include <cstdint>

#define HDIM 128
#define SPAD 40

// ---------------- static scratch ----------------
#define NA_MAX 50000
#define NB_MAX 30000
#define EA_MAX 600000
#define EB_MAX 300000

__device__ __nv_bfloat16 g_XhiA[NA_MAX * 256];
__device__ __nv_bfloat16 g_XloA[NA_MAX * 256];
__device__ float g_YA[NA_MAX * HDIM];
__device__ __nv_bfloat16 g_XhiB[NB_MAX * HDIM];
__device__ __nv_bfloat16 g_XloB[NB_MAX * HDIM];
__device__ float g_YB[NB_MAX * HDIM];

// per-(ntype,layer) weight buffers [N][K]
__device__ __nv_bfloat16 g_WhiA0[256 * HDIM];
__device__ __nv_bfloat16 g_WloA0[256 * HDIM];
__device__ __nv_bfloat16 g_WhiA1[HDIM * HDIM];
__device__ __nv_bfloat16 g_WloA1[HDIM * HDIM];
__device__ __nv_bfloat16 g_WhiB0[HDIM * HDIM];
__device__ __nv_bfloat16 g_WloB0[HDIM * HDIM];
__device__ __nv_bfloat16 g_WhiB1[HDIM * HDIM];
__device__ __nv_bfloat16 g_WloB1[HDIM * HDIM];

__device__ int g_cntOutA[NA_MAX];
__device__ int g_cntInA[NA_MAX];
__device__ int g_fillA[NA_MAX];
__device__ int g_rowpA[NA_MAX + 1];
__device__ int g_colA[EA_MAX];
__device__ float g_nsA[NA_MAX];
__device__ float g_ndA[NA_MAX];

__device__ int g_cntOutB[NB_MAX];
__device__ int g_cntInB[NB_MAX];
__device__ int g_fillB[NB_MAX];
__device__ int g_rowpB[NB_MAX + 1];
__device__ int g_colB[EB_MAX];
__device__ float g_nsB[NB_MAX];
__device__ float g_ndB[NB_MAX];

__device__ int g_bsumA[64];
__device__ int g_bsumB[64];

// ---------------- side streams (created pre-main) ----------------
namespace {
struct StreamInit {
    cudaStream_t s2, s3;
    cudaEvent_t evFork, evNS, evW, evCSR, evJoin;
    StreamInit() {
        cudaStreamCreateWithFlags(&s2, cudaStreamNonBlocking);
        cudaStreamCreateWithFlags(&s3, cudaStreamNonBlocking);
        cudaEventCreateWithFlags(&evFork, cudaEventDisableTiming);
        cudaEventCreateWithFlags(&evNS, cudaEventDisableTiming);
        cudaEventCreateWithFlags(&evW, cudaEventDisableTiming);
        cudaEventCreateWithFlags(&evCSR, cudaEventDisableTiming);
        cudaEventCreateWithFlags(&evJoin, cudaEventDisableTiming);
    }
};
StreamInit g_si;
}

// ---------------- prep kernels ----------------
__global__ void zero2_kernel(int* a, int na, int* b, int nb) {
    int i = blockIdx.x * blockDim.x + threadIdx.x;
    if (i < na) a[i] = 0;
    if (i < nb) b[i] = 0;
}

__global__ void zero4_kernel(int* a0, int* a1, int na, int* b0, int* b1, int nb) {
    int i = blockIdx.x * blockDim.x + threadIdx.x;
    if (i < na) { a0[i] = 0; a1[i] = 0; }
    if (i < nb) { b0[i] = 0; b1[i] = 0; }
}

__global__ void countOut_both_kernel(const int* __restrict__ srcA, int EA, int* cntOutA,
                                     const int* __restrict__ srcB, int EB, int* cntOutB) {
    int i = blockIdx.x * blockDim.x + threadIdx.x;
    if (i < EA) atomicAdd(&cntOutA[srcA[i]], 1);
    if (i < EB) atomicAdd(&cntOutB[srcB[i]], 1);
}

__global__ void countIn_both_kernel(const int* __restrict__ dstA, int EA, int* cntInA,
                                    const int* __restrict__ dstB, int EB, int* cntInB) {
    int i = blockIdx.x * blockDim.x + threadIdx.x;
    if (i < EA) atomicAdd(&cntInA[dstA[i]], 1);
    if (i < EB) atomicAdd(&cntInB[dstB[i]], 1);
}

__global__ void ns_both_kernel(const int* __restrict__ coA, float* nsA, int na,
                               const int* __restrict__ coB, float* nsB, int nb) {
    int i = blockIdx.x * blockDim.x + threadIdx.x;
    if (i < na) nsA[i] = rsqrtf((float)(coA[i] + 1));
    if (i < nb) nsB[i] = rsqrtf((float)(coB[i] + 1));
}

__global__ void nd_both_kernel(const int* __restrict__ ciA, float* ndA, int na,
                               const int* __restrict__ ciB, float* ndB, int nb) {
    int i = blockIdx.x * blockDim.x + threadIdx.x;
    if (i < na) ndA[i] = rsqrtf((float)(ciA[i] + 1));
    if (i < nb) ndB[i] = rsqrtf((float)(ciB[i] + 1));
}

// ---- multi-block scan, 3 phases ----
__device__ __forceinline__ int block_scan_1024(int x, int* warpsum) {
    const int tid = threadIdx.x;
    const int lane = tid & 31;
    const int wid = tid >> 5;
    #pragma unroll
    for (int d = 1; d < 32; d <<= 1) {
        int y = __shfl_up_sync(0xFFFFFFFFu, x, d);
        if (lane >= d) x += y;
    }
    if (lane == 31) warpsum[wid] = x;
    __syncthreads();
    if (wid == 0) {
        int w = warpsum[lane];
        #pragma unroll
        for (int d = 1; d < 32; d <<= 1) {
            int y = __shfl_up_sync(0xFFFFFFFFu, w, d);
            if (lane >= d) w += y;
        }
        warpsum[lane] = w;
    }
    __syncthreads();
    return x + (wid ? warpsum[wid - 1] : 0);
}

__global__ void scan1_kernel(const int* __restrict__ cntA, int* rowpA, int na, int nblkA,
                             const int* __restrict__ cntB, int* rowpB, int nb,
                             int* bsumA, int* bsumB) {
    __shared__ int warpsum[32];
    int blk = blockIdx.x;
    const int* cnt; int* rowp; int n; int* bsum; int cblk;
    if (blk < nblkA) { cnt = cntA; rowp = rowpA; n = na; bsum = bsumA; cblk = blk; }
    else             { cnt = cntB; rowp = rowpB; n = nb; bsum = bsumB; cblk = blk - nblkA; }
    const int tid = threadIdx.x;
    int i = cblk * 1024 + tid;
    int x = (i < n) ? cnt[i] : 0;
    int inc = block_scan_1024(x, warpsum);
    if (i < n) rowp[i + 1] = inc;
    if (tid == 1023) bsum[cblk] = inc;
    if (cblk == 0 && tid == 0) rowp[0] = 0;
}

__global__ void scan2_kernel(int* bsumA, int nblkA, int* bsumB, int nblkB) {
    __shared__ int warpsum[32];
    int* bsum = (blockIdx.x == 0) ? bsumA : bsumB;
    int nblk = (blockIdx.x == 0) ? nblkA : nblkB;
    const int tid = threadIdx.x;
    int x = (tid < nblk) ? bsum[tid] : 0;
    int inc = block_scan_1024(x, warpsum);
    if (tid < nblk) bsum[tid] = inc - x;  // exclusive
}

__global__ void scan3_kernel(int* rowpA, int na, int nblkA,
                             int* rowpB, int nb,
                             const int* __restrict__ bsumA, const int* __restrict__ bsumB) {
    int blk = blockIdx.x;
    int* rowp; int n; const int* bsum; int cblk;
    if (blk < nblkA) { rowp = rowpA; n = na; bsum = bsumA; cblk = blk; }
    else             { rowp = rowpB; n = nb; bsum = bsumB; cblk = blk - nblkA; }
    int off = __ldg(&bsum[cblk]);
    int i = cblk * 1024 + threadIdx.x;
    if (i < n) rowp[i + 1] += off;
}

__global__ void csr_fill_both_kernel(const int* __restrict__ srcA, const int* __restrict__ dstA,
                                     int EA, const int* __restrict__ rowpA, int* fillA, int* colA,
                                     const int* __restrict__ srcB, const int* __restrict__ dstB,
                                     int EB, const int* __restrict__ rowpB, int* fillB, int* colB) {
    int i = blockIdx.x * blockDim.x + threadIdx.x;
    if (i < EA) {
        int d = dstA[i];
        int pos = atomicAdd(&fillA[d], 1);
        colA[rowpA[d] + pos] = srcA[i];
    }
    if (i < EB) {
        int d = dstB[i];
        int pos = atomicAdd(&fillB[d], 1);
        colB[rowpB[d] + pos] = srcB[i];
    }
}

// ---------------- bf16 split helpers ----------------
__device__ __forceinline__ void split_bf16(float v, __nv_bfloat16& hi, __nv_bfloat16& lo) {
    hi = __float2bfloat16(v);
    lo = __float2bfloat16(v - __bfloat162float(hi));
}

__global__ void convert_feat_kernel(const float* __restrict__ X, const float* __restrict__ ns,
                                    __nv_bfloat16* __restrict__ Xhi, __nv_bfloat16* __restrict__ Xlo,
                                    int nquads, int kqshift) {
    int q = blockIdx.x * blockDim.x + threadIdx.x;
    if (q >= nquads) return;
    int row = q >> kqshift;
    float s = ns[row];
    float4 v = ((const float4*)X)[q];
    union { ushort4 u; __nv_bfloat16 b[4]; } H, L;
    split_bf16(v.x * s, H.b[0], L.b[0]);
    split_bf16(v.y * s, H.b[1], L.b[1]);
    split_bf16(v.z * s, H.b[2], L.b[2]);
    split_bf16(v.w * s, H.b[3], L.b[3]);
    ((ushort4*)Xhi)[q] = H.u;
    ((ushort4*)Xlo)[q] = L.u;
}

__device__ __forceinline__ void convW_one(const float* W, __nv_bfloat16* Whi,
                                          __nv_bfloat16* Wlo, int idx, int K) {
    int k = idx >> 7;
    int n = idx & 127;
    __nv_bfloat16 hi, lo;
    split_bf16(W[idx], hi, lo);
    Whi[n * K + k] = hi;
    Wlo[n * K + k] = lo;
}

// all 4 weight conversions in one launch
__global__ void convW_all_kernel(const float* __restrict__ Wa0, const float* __restrict__ Wa1,
                                 const float* __restrict__ Wb0, const float* __restrict__ Wb1,
                                 __nv_bfloat16* WhiA0, __nv_bfloat16* WloA0,
                                 __nv_bfloat16* WhiA1, __nv_bfloat16* WloA1,
                                 __nv_bfloat16* WhiB0, __nv_bfloat16* WloB0,
                                 __nv_bfloat16* WhiB1, __nv_bfloat16* WloB1,
                                 int DA, int DB, int H) {
    int idx = blockIdx.x * blockDim.x + threadIdx.x;
    int sz0 = DA * H, sz1 = H * H, sz2 = DB * H;
    if (idx < sz0) { convW_one(Wa0, WhiA0, WloA0, idx, DA); return; }
    idx -= sz0;
    if (idx < sz1) { convW_one(Wa1, WhiA1, WloA1, idx, H); return; }
    idx -= sz1;
    if (idx < sz2) { convW_one(Wb0, WhiB0, WloB0, idx, DB); return; }
    idx -= sz2;
    if (idx < sz1) { convW_one(Wb1, WhiB1, WloB1, idx, H); }
}

// ---------------- MMA / LDSM / cp.async primitives ----------------
__device__ __forceinline__ void mma_bf16(float& d0, float& d1, float& d2, float& d3,
                                         unsigned a0, unsigned a1, unsigned a2, unsigned a3,
                                         unsigned b0, unsigned b1) {
    asm volatile(
        "mma.sync.aligned.m16n8k16.row.col.f32.bf16.bf16.f32 "
        "{%0,%1,%2,%3}, {%4,%5,%6,%7}, {%8,%9}, {%0,%1,%2,%3};"
        : "+f"(d0), "+f"(d1), "+f"(d2), "+f"(d3)
        : "r"(a0), "r"(a1), "r"(a2), "r"(a3), "r"(b0), "r"(b1));
}

__device__ __forceinline__ void ldsm4(uint32_t addr, unsigned& r0, unsigned& r1,
                                      unsigned& r2, unsigned& r3) {
    asm volatile("ldmatrix.sync.aligned.m8n8.x4.shared.b16 {%0,%1,%2,%3}, [%4];"
                 : "=r"(r0), "=r"(r1), "=r"(r2), "=r"(r3) : "r"(addr));
}

__device__ __forceinline__ void cp16(uint32_t smem_addr, const void* gmem, bool pred) {
    int sz = pred ? 16 : 0;
    asm volatile("cp.async.cg.shared.global [%0], [%1], 16, %2;"
                 :: "r"(smem_addr), "l"(gmem), "r"(sz));
}
__device__ __forceinline__ void cp_commit() {
    asm volatile("cp.async.commit_group;");
}
__device__ __forceinline__ void cp_wait1() {
    asm volatile("cp.async.wait_group 1;");
}

// ---------------- bf16-split tensor-core GEMM ----------------
#define STAGE_ELE (128 * SPAD)
#define STAGE_BYTES (STAGE_ELE * 2)
#define GEMM_SMEM (4 * 2 * STAGE_BYTES)  // 81920 B

__global__ __launch_bounds__(256) void gemm_bf16_kernel(
    const __nv_bfloat16* __restrict__ Ahi, const __nv_bfloat16* __restrict__ Alo,
    const __nv_bfloat16* __restrict__ Bhi, const __nv_bfloat16* __restrict__ Blo,
    float* __restrict__ Y, int M, int K) {
    extern __shared__ __align__(16) char dynsmem[];
    __nv_bfloat16* sAhi = (__nv_bfloat16*)dynsmem;
    __nv_bfloat16* sAlo = sAhi + 2 * STAGE_ELE;
    __nv_bfloat16* sBhi = sAlo + 2 * STAGE_ELE;
    __nv_bfloat16* sBlo = sBhi + 2 * STAGE_ELE;

    const int tid = threadIdx.x;
    const int wid = tid >> 5;
    const int lane = tid & 31;
    const int warpM = wid >> 2;
    const int warpN = wid & 3;
    const int block_row = blockIdx.x * 128;

    float acc[4][4][4];
    #pragma unroll
    for (int i = 0; i < 4; i++)
        #pragma unroll
        for (int j = 0; j < 4; j++)
            #pragma unroll
            for (int c = 0; c < 4; c++) acc[i][j][c] = 0.0f;

    const int r0 = tid >> 2, kc0 = (tid & 3) * 8;
    const int r1 = r0 + 64;
    const int gr0 = block_row + r0;
    const int gr1 = block_row + r1;
    const bool v0 = gr0 < M;
    const bool v1 = gr1 < M;

    const uint32_t bAhi = (uint32_t)__cvta_generic_to_shared(sAhi);
    const uint32_t bAlo = (uint32_t)__cvta_generic_to_shared(sAlo);
    const uint32_t bBhi = (uint32_t)__cvta_generic_to_shared(sBhi);
    const uint32_t bBlo = (uint32_t)__cvta_generic_to_shared(sBlo);

    const uint32_t st_off0 = (uint32_t)(r0 * SPAD + kc0) * 2;
    const uint32_t st_off1 = (uint32_t)(r1 * SPAD + kc0) * 2;

    const int aRow = warpM * 64 + (lane & 15);
    const int aColOff = (lane >> 4) * 8;
    const uint32_t offA = (uint32_t)(aRow * SPAD + aColOff) * 2;
    const int bRow = warpN * 32 + ((lane >> 4) & 1) * 8 + (lane & 7);
    const int bColOff = ((lane >> 3) & 1) * 8;
    const uint32_t offB = (uint32_t)(bRow * SPAD + bColOff) * 2;

    const int ntiles = K >> 5;

    {
        cp16(bAhi + st_off0, &Ahi[(size_t)gr0 * K + kc0], v0);
        cp16(bAlo + st_off0, &Alo[(size_t)gr0 * K + kc0], v0);
        cp16(bAhi + st_off1, &Ahi[(size_t)gr1 * K + kc0], v1);
        cp16(bAlo + st_off1, &Alo[(size_t)gr1 * K + kc0], v1);
        cp16(bBhi + st_off0, &Bhi[(size_t)r0 * K + kc0], true);
        cp16(bBlo + st_off0, &Blo[(size_t)r0 * K + kc0], true);
        cp16(bBhi + st_off1, &Bhi[(size_t)r1 * K + kc0], true);
        cp16(bBlo + st_off1, &Blo[(size_t)r1 * K + kc0], true);
    }
    cp_commit();

    for (int t = 0; t < ntiles; t++) {
        if (t + 1 < ntiles) {
            const int k0 = (t + 1) << 5;
            const uint32_t sb = (uint32_t)((t + 1) & 1) * STAGE_BYTES;
            cp16(bAhi + sb + st_off0, &Ahi[(size_t)gr0 * K + k0 + kc0], v0);
            cp16(bAlo + sb + st_off0, &Alo[(size_t)gr0 * K + k0 + kc0], v0);
            cp16(bAhi + sb + st_off1, &Ahi[(size_t)gr1 * K + k0 + kc0], v1);
            cp16(bAlo + sb + st_off1, &Alo[(size_t)gr1 * K + k0 + kc0], v1);
            cp16(bBhi + sb + st_off0, &Bhi[(size_t)r0 * K + k0 + kc0], true);
            cp16(bBlo + sb + st_off0, &Blo[(size_t)r0 * K + k0 + kc0], true);
            cp16(bBhi + sb + st_off1, &Bhi[(size_t)r1 * K + k0 + kc0], true);
            cp16(bBlo + sb + st_off1, &Blo[(size_t)r1 * K + k0 + kc0], true);
        }
        cp_commit();
        cp_wait1();
        __syncthreads();

        const uint32_t sb = (uint32_t)(t & 1) * STAGE_BYTES;

        #pragma unroll
        for (int kk = 0; kk < 32; kk += 16) {
            unsigned bh[4][2], bl[4][2];
            #pragma unroll
            for (int pair = 0; pair < 2; pair++) {
                const uint32_t ad = sb + offB + (uint32_t)(pair * 16 * SPAD + kk) * 2;
                ldsm4(bBhi + ad, bh[pair * 2][0], bh[pair * 2][1],
                      bh[pair * 2 + 1][0], bh[pair * 2 + 1][1]);
                ldsm4(bBlo + ad, bl[pair * 2][0], bl[pair * 2][1],
                      bl[pair * 2 + 1][0], bl[pair * 2 + 1][1]);
            }
            #pragma unroll
            for (int mt = 0; mt < 4; mt++) {
                const uint32_t ad = sb + offA + (uint32_t)(mt * 16 * SPAD + kk) * 2;
                unsigned a0, a1, a2, a3, l0, l1, l2, l3;
                ldsm4(bAhi + ad, a0, a1, a2, a3);
                ldsm4(bAlo + ad, l0, l1, l2, l3);
                #pragma unroll
                for (int nt = 0; nt < 4; nt++) {
                    mma_bf16(acc[mt][nt][0], acc[mt][nt][1], acc[mt][nt][2], acc[mt][nt][3],
                             a0, a1, a2, a3, bh[nt][0], bh[nt][1]);
                    mma_bf16(acc[mt][nt][0], acc[mt][nt][1], acc[mt][nt][2], acc[mt][nt][3],
                             a0, a1, a2, a3, bl[nt][0], bl[nt][1]);
                    mma_bf16(acc[mt][nt][0], acc[mt][nt][1], acc[mt][nt][2], acc[mt][nt][3],
                             l0, l1, l2, l3, bh[nt][0], bh[nt][1]);
                }
            }
        }
        __syncthreads();
    }

    const int g = lane >> 2;
    const int tg = lane & 3;
    #pragma unroll
    for (int mt = 0; mt < 4; mt++) {
        #pragma unroll
        for (int nt = 0; nt < 4; nt++) {
            int r = block_row + warpM * 64 + mt * 16 + g;
            int c = warpN * 32 + nt * 8 + tg * 2;
            if (r < M) {
                float2 v0m = make_float2(acc[mt][nt][0], acc[mt][nt][1]);
                *(float2*)&Y[(size_t)r * HDIM + c] = v0m;
            }
            if (r + 8 < M) {
                float2 v1m = make_float2(acc[mt][nt][2], acc[mt][nt][3]);
                *(float2*)&Y[(size_t)(r + 8) * HDIM + c] = v1m;
            }
        }
    }
}

// ---------------- aggregation (unroll-4 gather) ----------------
__global__ __launch_bounds__(256) void aggregate_kernel(
    const float* __restrict__ y,
    const int* __restrict__ rowp, const int* __restrict__ col,
    const float* __restrict__ nd, const float* __restrict__ ns,
    const float* __restrict__ bias,
    float* __restrict__ out_f32,
    __nv_bfloat16* __restrict__ out_hi, __nv_bfloat16* __restrict__ out_lo,
    int n, int mode) {
    int warp = (blockIdx.x * blockDim.x + threadIdx.x) >> 5;
    int lane = threadIdx.x & 31;
    if (warp >= n) return;

    float4 acc = *((const float4*)(y + (size_t)warp * HDIM) + lane);  // self loop

    const int s = __ldg(&rowp[warp]);
    const int e = __ldg(&rowp[warp + 1]);
    int i = s;
    for (; i + 4 <= e; i += 4) {
        int nb0 = __ldg(&col[i]);
        int nb1 = __ldg(&col[i + 1]);
        int nb2 = __ldg(&col[i + 2]);
        int nb3 = __ldg(&col[i + 3]);
        float4 v0 = *((const float4*)(y + (size_t)nb0 * HDIM) + lane);
        float4 v1 = *((const float4*)(y + (size_t)nb1 * HDIM) + lane);
        float4 v2 = *((const float4*)(y + (size_t)nb2 * HDIM) + lane);
        float4 v3 = *((const float4*)(y + (size_t)nb3 * HDIM) + lane);
        acc.x += (v0.x + v1.x) + (v2.x + v3.x);
        acc.y += (v0.y + v1.y) + (v2.y + v3.y);
        acc.z += (v0.z + v1.z) + (v2.z + v3.z);
        acc.w += (v0.w + v1.w) + (v2.w + v3.w);
    }
    for (; i < e; i++) {
        int nb = __ldg(&col[i]);
        float4 v = *((const float4*)(y + (size_t)nb * HDIM) + lane);
        acc.x += v.x; acc.y += v.y; acc.z += v.z; acc.w += v.w;
    }

    float sc = nd[warp];
    float4 b = ((const float4*)bias)[lane];
    float4 r;
    r.x = fmaf(acc.x, sc, b.x);
    r.y = fmaf(acc.y, sc, b.y);
    r.z = fmaf(acc.z, sc, b.z);
    r.w = fmaf(acc.w, sc, b.w);
    if (mode) {
        r.x = fmaxf(r.x, 0.f); r.y = fmaxf(r.y, 0.f);
        r.z = fmaxf(r.z, 0.f); r.w = fmaxf(r.w, 0.f);
        float nsv = ns[warp];
        union { ushort4 u; __nv_bfloat16 bb[4]; } H, L;
        split_bf16(r.x * nsv, H.bb[0], L.bb[0]);
        split_bf16(r.y * nsv, H.bb[1], L.bb[1]);
        split_bf16(r.z * nsv, H.bb[2], L.bb[2]);
        split_bf16(r.w * nsv, H.bb[3], L.bb[3]);
        *(ushort4*)&out_hi[(size_t)warp * HDIM + lane * 4] = H.u;
        *(ushort4*)&out_lo[(size_t)warp * HDIM + lane * 4] = L.u;
    } else {
        ((float4*)(out_f32 + (size_t)warp * HDIM))[lane] = r;
    }
}

// ---------------- host orchestration ----------------
static inline int cdiv(int a, int b) { return (a + b - 1) / b; }

extern "C" void kernel_launch(void* const* d_in, const int* in_sizes, int n_in,
                              void* d_out, int out_size) {
    const float* feat_a = (const float*)d_in[0];
    const float* feat_b = (const float*)d_in[1];
    const int* src_a = (const int*)d_in[2];
    const int* dst_a = (const int*)d_in[3];
    const int* src_b = (const int*)d_in[4];
    const int* dst_b = (const int*)d_in[5];
    const float* Wa0 = (const float*)d_in[6];
    const float* ba0 = (const float*)d_in[7];
    const float* Wa1 = (const float*)d_in[8];
    const float* ba1 = (const float*)d_in[9];
    const float* Wb0 = (const float*)d_in[10];
    const float* bb0 = (const float*)d_in[11];
    const float* Wb1 = (const float*)d_in[12];
    const float* bb1 = (const float*)d_in[13];

    const int H = in_sizes[7];
    const int DA = in_sizes[6] / H;
    const int NA = in_sizes[0] / DA;
    const int EA = in_sizes[2];
    const int DB = in_sizes[10] / H;
    const int NB = in_sizes[1] / DB;
    const int EB = in_sizes[4];

    float* out = (float*)d_out;
    float* out_a = out;
    float* out_b = out + (size_t)NA * HDIM;

    __nv_bfloat16 *XhiA, *XloA, *XhiB, *XloB;
    __nv_bfloat16 *WhiA0, *WloA0, *WhiA1, *WloA1, *WhiB0, *WloB0, *WhiB1, *WloB1;
    float *YA, *YB, *nsA, *ndA, *nsB, *ndB;
    int *cntOutA, *cntInA, *fillA, *rowpA, *colA;
    int *cntOutB, *cntInB, *fillB, *rowpB, *colB;
    int *bsumA, *bsumB;
    cudaGetSymbolAddress((void**)&XhiA, g_XhiA);
    cudaGetSymbolAddress((void**)&XloA, g_XloA);
    cudaGetSymbolAddress((void**)&YA, g_YA);
    cudaGetSymbolAddress((void**)&XhiB, g_XhiB);
    cudaGetSymbolAddress((void**)&XloB, g_XloB);
    cudaGetSymbolAddress((void**)&YB, g_YB);
    cudaGetSymbolAddress((void**)&WhiA0, g_WhiA0);
    cudaGetSymbolAddress((void**)&WloA0, g_WloA0);
    cudaGetSymbolAddress((void**)&WhiA1, g_WhiA1);
    cudaGetSymbolAddress((void**)&WloA1, g_WloA1);
    cudaGetSymbolAddress((void**)&WhiB0, g_WhiB0);
    cudaGetSymbolAddress((void**)&WloB0, g_WloB0);
    cudaGetSymbolAddress((void**)&WhiB1, g_WhiB1);
    cudaGetSymbolAddress((void**)&WloB1, g_WloB1);
    cudaGetSymbolAddress((void**)&nsA, g_nsA);
    cudaGetSymbolAddress((void**)&ndA, g_ndA);
    cudaGetSymbolAddress((void**)&nsB, g_nsB);
    cudaGetSymbolAddress((void**)&ndB, g_ndB);
    cudaGetSymbolAddress((void**)&cntOutA, g_cntOutA);
    cudaGetSymbolAddress((void**)&cntInA, g_cntInA);
    cudaGetSymbolAddress((void**)&fillA, g_fillA);
    cudaGetSymbolAddress((void**)&rowpA, g_rowpA);
    cudaGetSymbolAddress((void**)&colA, g_colA);
    cudaGetSymbolAddress((void**)&cntOutB, g_cntOutB);
    cudaGetSymbolAddress((void**)&cntInB, g_cntInB);
    cudaGetSymbolAddress((void**)&fillB, g_fillB);
    cudaGetSymbolAddress((void**)&rowpB, g_rowpB);
    cudaGetSymbolAddress((void**)&colB, g_colB);
    cudaGetSymbolAddress((void**)&bsumA, g_bsumA);
    cudaGetSymbolAddress((void**)&bsumB, g_bsumB);

    cudaFuncSetAttribute(gemm_bf16_kernel,
                         cudaFuncAttributeMaxDynamicSharedMemorySize, GEMM_SMEM);

    const int T = 256;
    const int nblkA = cdiv(NA, 1024);
    const int nblkB = cdiv(NB, 1024);
    cudaStream_t s2 = g_si.s2;
    cudaStream_t s3 = g_si.s3;

    // ---- fork at the very start ----
    cudaEventRecord(g_si.evFork, 0);
    cudaStreamWaitEvent(s2, g_si.evFork, 0);
    cudaStreamWaitEvent(s3, g_si.evFork, 0);

    // ===== s2: all weight conversions first (no dependencies) =====
    {
        int total = DA * H + H * H + DB * H + H * H;
        convW_all_kernel<<<cdiv(total, T), T, 0, s2>>>(Wa0, Wa1, Wb0, Wb1,
                                                       WhiA0, WloA0, WhiA1, WloA1,
                                                       WhiB0, WloB0, WhiB1, WloB1,
                                                       DA, DB, H);
    }
    cudaEventRecord(g_si.evW, s2);

    // ===== stream0: out-degree -> ns -> A conversion =====
    zero2_kernel<<<cdiv(NA, T), T>>>(cntOutA, NA, cntOutB, NB);
    countOut_both_kernel<<<cdiv(EA > EB ? EA : EB, T), T>>>(src_a, EA, cntOutA,
                                                            src_b, EB, cntOutB);
    ns_both_kernel<<<cdiv(NA > NB ? NA : NB, T), T>>>(cntOutA, nsA, NA, cntOutB, nsB, NB);
    cudaEventRecord(g_si.evNS, 0);

    // ===== s3: in-degree -> nd -> CSR =====
    zero4_kernel<<<cdiv(NA, T), T, 0, s3>>>(cntInA, fillA, NA, cntInB, fillB, NB);
    countIn_both_kernel<<<cdiv(EA > EB ? EA : EB, T), T, 0, s3>>>(dst_a, EA, cntInA,
                                                                  dst_b, EB, cntInB);
    nd_both_kernel<<<cdiv(NA > NB ? NA : NB, T), T, 0, s3>>>(cntInA, ndA, NA, cntInB, ndB, NB);
    scan1_kernel<<<nblkA + nblkB, 1024, 0, s3>>>(cntInA, rowpA, NA, nblkA,
                                                 cntInB, rowpB, NB, bsumA, bsumB);
    scan2_kernel<<<2, 1024, 0, s3>>>(bsumA, nblkA, bsumB, nblkB);
    scan3_kernel<<<nblkA + nblkB, 1024, 0, s3>>>(rowpA, NA, nblkA, rowpB, NB, bsumA, bsumB);
    csr_fill_both_kernel<<<cdiv(EA > EB ? EA : EB, T), T, 0, s3>>>(
        src_a, dst_a, EA, rowpA, fillA, colA,
        src_b, dst_b, EB, rowpB, fillB, colB);
    cudaEventRecord(g_si.evCSR, s3);

    // ===== stream0: ntype A =====
    {
        int nq = NA * DA / 4;
        int kqshift = (DA == 256) ? 6 : 5;
        convert_feat_kernel<<<cdiv(nq, T), T>>>(feat_a, nsA, XhiA, XloA, nq, kqshift);
    }
    cudaStreamWaitEvent((cudaStream_t)0, g_si.evW, 0);
    gemm_bf16_kernel<<<cdiv(NA, 128), 256, GEMM_SMEM>>>(XhiA, XloA, WhiA0, WloA0, YA, NA, DA);
    cudaStreamWaitEvent((cudaStream_t)0, g_si.evCSR, 0);
    aggregate_kernel<<<cdiv(NA * 32, 256), 256>>>(YA, rowpA, colA, ndA, nsA, ba0,
                                                  nullptr, XhiA, XloA, NA, 1);
    gemm_bf16_kernel<<<cdiv(NA, 128), 256, GEMM_SMEM>>>(XhiA, XloA, WhiA1, WloA1, YA, NA, H);
    aggregate_kernel<<<cdiv(NA * 32, 256), 256>>>(YA, rowpA, colA, ndA, nsA, ba1,
                                                  out_a, nullptr, nullptr, NA, 0);

    // ===== s2: ntype B (after its convW; waits for nsB) =====
    cudaStreamWaitEvent(s2, g_si.evNS, 0);
    {
        int nq = NB * DB / 4;
        int kqshift = (DB == 256) ? 6 : 5;
        convert_feat_kernel<<<cdiv(nq, T), T, 0, s2>>>(feat_b, nsB, XhiB, XloB, nq, kqshift);
    }
    gemm_bf16_kernel<<<cdiv(NB, 128), 256, GEMM_SMEM, s2>>>(XhiB, XloB, WhiB0, WloB0, YB, NB, DB);
    cudaStreamWaitEvent(s2, g_si.evCSR, 0);
    aggregate_kernel<<<cdiv(NB * 32, 256), 256, 0, s2>>>(YB, rowpB, colB, ndB, nsB, bb0,
                                                         nullptr, XhiB, XloB, NB, 1);
    gemm_bf16_kernel<<<cdiv(NB, 128), 256, GEMM_SMEM, s2>>>(XhiB, XloB, WhiB1, WloB1, YB, NB, H);
    aggregate_kernel<<<cdiv(NB * 32, 256), 256, 0, s2>>>(YB, rowpB, colB, ndB, nsB, bb1,
                                                         out_b, nullptr, nullptr, NB, 0);

    // ---- join back to legacy stream ----
    cudaEventRecord(g_si.evJoin, s2);
    cudaStreamWaitEvent((cudaStream_t)0, g_si.evJoin, 0);

    (void)n_in; (void)out_size;
}

// round 17
// speedup vs baseline: 1.0112x; 1.0112x over previous
#include <cuda_runtime.h>
#include <cuda_bf16.h>
#include <cstdint>

#define HDIM 128
#define SPAD 40

// ---------------- static scratch ----------------
#define NA_MAX 50000
#define NB_MAX 30000
#define EA_MAX 600000
#define EB_MAX 300000

__device__ __nv_bfloat16 g_XhiA[NA_MAX * 256];
__device__ __nv_bfloat16 g_XloA[NA_MAX * 256];
__device__ float g_YA[NA_MAX * HDIM];
__device__ __nv_bfloat16 g_XhiB[NB_MAX * HDIM];
__device__ __nv_bfloat16 g_XloB[NB_MAX * HDIM];
__device__ float g_YB[NB_MAX * HDIM];

// per-(ntype,layer) weight buffers [N][K]
__device__ __nv_bfloat16 g_WhiA0[256 * HDIM];
__device__ __nv_bfloat16 g_WloA0[256 * HDIM];
__device__ __nv_bfloat16 g_WhiA1[HDIM * HDIM];
__device__ __nv_bfloat16 g_WloA1[HDIM * HDIM];
__device__ __nv_bfloat16 g_WhiB0[HDIM * HDIM];
__device__ __nv_bfloat16 g_WloB0[HDIM * HDIM];
__device__ __nv_bfloat16 g_WhiB1[HDIM * HDIM];
__device__ __nv_bfloat16 g_WloB1[HDIM * HDIM];

__device__ int g_cntOutA[NA_MAX];
__device__ int g_cntInA[NA_MAX];
__device__ int g_fillA[NA_MAX];
__device__ int g_rowpA[NA_MAX + 1];
__device__ int g_colA[EA_MAX];
__device__ float g_nsA[NA_MAX];
__device__ float g_ndA[NA_MAX];

__device__ int g_cntOutB[NB_MAX];
__device__ int g_cntInB[NB_MAX];
__device__ int g_fillB[NB_MAX];
__device__ int g_rowpB[NB_MAX + 1];
__device__ int g_colB[EB_MAX];
__device__ float g_nsB[NB_MAX];
__device__ float g_ndB[NB_MAX];

__device__ int g_bsumA[64];
__device__ int g_bsumB[64];

// ---------------- side streams (created pre-main) ----------------
namespace {
struct StreamInit {
    cudaStream_t s2, s3;
    cudaEvent_t evFork, evW, evCSR, evJoin;
    StreamInit() {
        cudaStreamCreateWithFlags(&s2, cudaStreamNonBlocking);
        cudaStreamCreateWithFlags(&s3, cudaStreamNonBlocking);
        cudaEventCreateWithFlags(&evFork, cudaEventDisableTiming);
        cudaEventCreateWithFlags(&evW, cudaEventDisableTiming);
        cudaEventCreateWithFlags(&evCSR, cudaEventDisableTiming);
        cudaEventCreateWithFlags(&evJoin, cudaEventDisableTiming);
    }
};
StreamInit g_si;
}

// ---------------- merged graph-prep kernels ----------------
__global__ void zero_all_kernel(int* a0, int* a1, int* a2, int na,
                                int* b0, int* b1, int* b2, int nb) {
    int i = blockIdx.x * blockDim.x + threadIdx.x;
    if (i < na) { a0[i] = 0; a1[i] = 0; a2[i] = 0; }
    if (i < nb) { b0[i] = 0; b1[i] = 0; b2[i] = 0; }
}

__global__ void count_deg_both_kernel(const int* __restrict__ srcA, const int* __restrict__ dstA,
                                      int EA, int* cntOutA, int* cntInA,
                                      const int* __restrict__ srcB, const int* __restrict__ dstB,
                                      int EB, int* cntOutB, int* cntInB) {
    int i = blockIdx.x * blockDim.x + threadIdx.x;
    if (i < EA) {
        atomicAdd(&cntOutA[srcA[i]], 1);
        atomicAdd(&cntInA[dstA[i]], 1);
    }
    if (i < EB) {
        atomicAdd(&cntOutB[srcB[i]], 1);
        atomicAdd(&cntInB[dstB[i]], 1);
    }
}

__global__ void norms_both_kernel(const int* __restrict__ coA, const int* __restrict__ ciA,
                                  float* nsA, float* ndA, int na,
                                  const int* __restrict__ coB, const int* __restrict__ ciB,
                                  float* nsB, float* ndB, int nb) {
    int i = blockIdx.x * blockDim.x + threadIdx.x;
    if (i < na) {
        nsA[i] = rsqrtf((float)(coA[i] + 1));
        ndA[i] = rsqrtf((float)(ciA[i] + 1));
    }
    if (i < nb) {
        nsB[i] = rsqrtf((float)(coB[i] + 1));
        ndB[i] = rsqrtf((float)(ciB[i] + 1));
    }
}

// ---- multi-block scan, 3 phases ----
__device__ __forceinline__ int block_scan_1024(int x, int* warpsum) {
    const int tid = threadIdx.x;
    const int lane = tid & 31;
    const int wid = tid >> 5;
    #pragma unroll
    for (int d = 1; d < 32; d <<= 1) {
        int y = __shfl_up_sync(0xFFFFFFFFu, x, d);
        if (lane >= d) x += y;
    }
    if (lane == 31) warpsum[wid] = x;
    __syncthreads();
    if (wid == 0) {
        int w = warpsum[lane];
        #pragma unroll
        for (int d = 1; d < 32; d <<= 1) {
            int y = __shfl_up_sync(0xFFFFFFFFu, w, d);
            if (lane >= d) w += y;
        }
        warpsum[lane] = w;
    }
    __syncthreads();
    return x + (wid ? warpsum[wid - 1] : 0);
}

__global__ void scan1_kernel(const int* __restrict__ cntA, int* rowpA, int na, int nblkA,
                             const int* __restrict__ cntB, int* rowpB, int nb,
                             int* bsumA, int* bsumB) {
    __shared__ int warpsum[32];
    int blk = blockIdx.x;
    const int* cnt; int* rowp; int n; int* bsum; int cblk;
    if (blk < nblkA) { cnt = cntA; rowp = rowpA; n = na; bsum = bsumA; cblk = blk; }
    else             { cnt = cntB; rowp = rowpB; n = nb; bsum = bsumB; cblk = blk - nblkA; }
    const int tid = threadIdx.x;
    int i = cblk * 1024 + tid;
    int x = (i < n) ? cnt[i] : 0;
    int inc = block_scan_1024(x, warpsum);
    if (i < n) rowp[i + 1] = inc;
    if (tid == 1023) bsum[cblk] = inc;
    if (cblk == 0 && tid == 0) rowp[0] = 0;
}

__global__ void scan2_kernel(int* bsumA, int nblkA, int* bsumB, int nblkB) {
    __shared__ int warpsum[32];
    int* bsum = (blockIdx.x == 0) ? bsumA : bsumB;
    int nblk = (blockIdx.x == 0) ? nblkA : nblkB;
    const int tid = threadIdx.x;
    int x = (tid < nblk) ? bsum[tid] : 0;
    int inc = block_scan_1024(x, warpsum);
    if (tid < nblk) bsum[tid] = inc - x;  // exclusive
}

__global__ void scan3_kernel(int* rowpA, int na, int nblkA,
                             int* rowpB, int nb,
                             const int* __restrict__ bsumA, const int* __restrict__ bsumB) {
    int blk = blockIdx.x;
    int* rowp; int n; const int* bsum; int cblk;
    if (blk < nblkA) { rowp = rowpA; n = na; bsum = bsumA; cblk = blk; }
    else             { rowp = rowpB; n = nb; bsum = bsumB; cblk = blk - nblkA; }
    int off = __ldg(&bsum[cblk]);
    int i = cblk * 1024 + threadIdx.x;
    if (i < n) rowp[i + 1] += off;
}

__global__ void csr_fill_both_kernel(const int* __restrict__ srcA, const int* __restrict__ dstA,
                                     int EA, const int* __restrict__ rowpA, int* fillA, int* colA,
                                     const int* __restrict__ srcB, const int* __restrict__ dstB,
                                     int EB, const int* __restrict__ rowpB, int* fillB, int* colB) {
    int i = blockIdx.x * blockDim.x + threadIdx.x;
    if (i < EA) {
        int d = dstA[i];
        int pos = atomicAdd(&fillA[d], 1);
        colA[rowpA[d] + pos] = srcA[i];
    }
    if (i < EB) {
        int d = dstB[i];
        int pos = atomicAdd(&fillB[d], 1);
        colB[rowpB[d] + pos] = srcB[i];
    }
}

// ---------------- bf16 split helpers ----------------
__device__ __forceinline__ void split_bf16(float v, __nv_bfloat16& hi, __nv_bfloat16& lo) {
    hi = __float2bfloat16(v);
    lo = __float2bfloat16(v - __bfloat162float(hi));
}

__global__ void convert_feat_kernel(const float* __restrict__ X, const float* __restrict__ ns,
                                    __nv_bfloat16* __restrict__ Xhi, __nv_bfloat16* __restrict__ Xlo,
                                    int nquads, int kqshift) {
    int q = blockIdx.x * blockDim.x + threadIdx.x;
    if (q >= nquads) return;
    int row = q >> kqshift;
    float s = ns[row];
    float4 v = ((const float4*)X)[q];
    union { ushort4 u; __nv_bfloat16 b[4]; } H, L;
    split_bf16(v.x * s, H.b[0], L.b[0]);
    split_bf16(v.y * s, H.b[1], L.b[1]);
    split_bf16(v.z * s, H.b[2], L.b[2]);
    split_bf16(v.w * s, H.b[3], L.b[3]);
    ((ushort4*)Xhi)[q] = H.u;
    ((ushort4*)Xlo)[q] = L.u;
}

__device__ __forceinline__ void convW_one(const float* W, __nv_bfloat16* Whi,
                                          __nv_bfloat16* Wlo, int idx, int K) {
    int k = idx >> 7;
    int n = idx & 127;
    __nv_bfloat16 hi, lo;
    split_bf16(W[idx], hi, lo);
    Whi[n * K + k] = hi;
    Wlo[n * K + k] = lo;
}

// all 4 weight conversions in one launch
__global__ void convW_all_kernel(const float* __restrict__ Wa0, const float* __restrict__ Wa1,
                                 const float* __restrict__ Wb0, const float* __restrict__ Wb1,
                                 __nv_bfloat16* WhiA0, __nv_bfloat16* WloA0,
                                 __nv_bfloat16* WhiA1, __nv_bfloat16* WloA1,
                                 __nv_bfloat16* WhiB0, __nv_bfloat16* WloB0,
                                 __nv_bfloat16* WhiB1, __nv_bfloat16* WloB1,
                                 int DA, int DB, int H) {
    int idx = blockIdx.x * blockDim.x + threadIdx.x;
    int sz0 = DA * H, sz1 = H * H, sz2 = DB * H;
    if (idx < sz0) { convW_one(Wa0, WhiA0, WloA0, idx, DA); return; }
    idx -= sz0;
    if (idx < sz1) { convW_one(Wa1, WhiA1, WloA1, idx, H); return; }
    idx -= sz1;
    if (idx < sz2) { convW_one(Wb0, WhiB0, WloB0, idx, DB); return; }
    idx -= sz2;
    if (idx < sz1) { convW_one(Wb1, WhiB1, WloB1, idx, H); }
}

// ---------------- MMA / LDSM / cp.async primitives ----------------
__device__ __forceinline__ void mma_bf16(float& d0, float& d1, float& d2, float& d3,
                                         unsigned a0, unsigned a1, unsigned a2, unsigned a3,
                                         unsigned b0, unsigned b1) {
    asm volatile(
        "mma.sync.aligned.m16n8k16.row.col.f32.bf16.bf16.f32 "
        "{%0,%1,%2,%3}, {%4,%5,%6,%7}, {%8,%9}, {%0,%1,%2,%3};"
        : "+f"(d0), "+f"(d1), "+f"(d2), "+f"(d3)
        : "r"(a0), "r"(a1), "r"(a2), "r"(a3), "r"(b0), "r"(b1));
}

__device__ __forceinline__ void ldsm4(uint32_t addr, unsigned& r0, unsigned& r1,
                                      unsigned& r2, unsigned& r3) {
    asm volatile("ldmatrix.sync.aligned.m8n8.x4.shared.b16 {%0,%1,%2,%3}, [%4];"
                 : "=r"(r0), "=r"(r1), "=r"(r2), "=r"(r3) : "r"(addr));
}

__device__ __forceinline__ void cp16(uint32_t smem_addr, const void* gmem, bool pred) {
    int sz = pred ? 16 : 0;
    asm volatile("cp.async.cg.shared.global [%0], [%1], 16, %2;"
                 :: "r"(smem_addr), "l"(gmem), "r"(sz));
}
__device__ __forceinline__ void cp_commit() {
    asm volatile("cp.async.commit_group;");
}
__device__ __forceinline__ void cp_wait1() {
    asm volatile("cp.async.wait_group 1;");
}

// ---------------- bf16-split tensor-core GEMM ----------------
#define STAGE_ELE (128 * SPAD)
#define STAGE_BYTES (STAGE_ELE * 2)
#define GEMM_SMEM (4 * 2 * STAGE_BYTES)  // 81920 B

__global__ __launch_bounds__(256) void gemm_bf16_kernel(
    const __nv_bfloat16* __restrict__ Ahi, const __nv_bfloat16* __restrict__ Alo,
    const __nv_bfloat16* __restrict__ Bhi, const __nv_bfloat16* __restrict__ Blo,
    float* __restrict__ Y, int M, int K) {
    extern __shared__ __align__(16) char dynsmem[];
    __nv_bfloat16* sAhi = (__nv_bfloat16*)dynsmem;
    __nv_bfloat16* sAlo = sAhi + 2 * STAGE_ELE;
    __nv_bfloat16* sBhi = sAlo + 2 * STAGE_ELE;
    __nv_bfloat16* sBlo = sBhi + 2 * STAGE_ELE;

    const int tid = threadIdx.x;
    const int wid = tid >> 5;
    const int lane = tid & 31;
    const int warpM = wid >> 2;
    const int warpN = wid & 3;
    const int block_row = blockIdx.x * 128;

    float acc[4][4][4];
    #pragma unroll
    for (int i = 0; i < 4; i++)
        #pragma unroll
        for (int j = 0; j < 4; j++)
            #pragma unroll
            for (int c = 0; c < 4; c++) acc[i][j][c] = 0.0f;

    const int r0 = tid >> 2, kc0 = (tid & 3) * 8;
    const int r1 = r0 + 64;
    const int gr0 = block_row + r0;
    const int gr1 = block_row + r1;
    const bool v0 = gr0 < M;
    const bool v1 = gr1 < M;

    const uint32_t bAhi = (uint32_t)__cvta_generic_to_shared(sAhi);
    const uint32_t bAlo = (uint32_t)__cvta_generic_to_shared(sAlo);
    const uint32_t bBhi = (uint32_t)__cvta_generic_to_shared(sBhi);
    const uint32_t bBlo = (uint32_t)__cvta_generic_to_shared(sBlo);

    const uint32_t st_off0 = (uint32_t)(r0 * SPAD + kc0) * 2;
    const uint32_t st_off1 = (uint32_t)(r1 * SPAD + kc0) * 2;

    const int aRow = warpM * 64 + (lane & 15);
    const int aColOff = (lane >> 4) * 8;
    const uint32_t offA = (uint32_t)(aRow * SPAD + aColOff) * 2;
    const int bRow = warpN * 32 + ((lane >> 4) & 1) * 8 + (lane & 7);
    const int bColOff = ((lane >> 3) & 1) * 8;
    const uint32_t offB = (uint32_t)(bRow * SPAD + bColOff) * 2;

    const int ntiles = K >> 5;

    {
        cp16(bAhi + st_off0, &Ahi[(size_t)gr0 * K + kc0], v0);
        cp16(bAlo + st_off0, &Alo[(size_t)gr0 * K + kc0], v0);
        cp16(bAhi + st_off1, &Ahi[(size_t)gr1 * K + kc0], v1);
        cp16(bAlo + st_off1, &Alo[(size_t)gr1 * K + kc0], v1);
        cp16(bBhi + st_off0, &Bhi[(size_t)r0 * K + kc0], true);
        cp16(bBlo + st_off0, &Blo[(size_t)r0 * K + kc0], true);
        cp16(bBhi + st_off1, &Bhi[(size_t)r1 * K + kc0], true);
        cp16(bBlo + st_off1, &Blo[(size_t)r1 * K + kc0], true);
    }
    cp_commit();

    for (int t = 0; t < ntiles; t++) {
        if (t + 1 < ntiles) {
            const int k0 = (t + 1) << 5;
            const uint32_t sb = (uint32_t)((t + 1) & 1) * STAGE_BYTES;
            cp16(bAhi + sb + st_off0, &Ahi[(size_t)gr0 * K + k0 + kc0], v0);
            cp16(bAlo + sb + st_off0, &Alo[(size_t)gr0 * K + k0 + kc0], v0);
            cp16(bAhi + sb + st_off1, &Ahi[(size_t)gr1 * K + k0 + kc0], v1);
            cp16(bAlo + sb + st_off1, &Alo[(size_t)gr1 * K + k0 + kc0], v1);
            cp16(bBhi + sb + st_off0, &Bhi[(size_t)r0 * K + k0 + kc0], true);
            cp16(bBlo + sb + st_off0, &Blo[(size_t)r0 * K + k0 + kc0], true);
            cp16(bBhi + sb + st_off1, &Bhi[(size_t)r1 * K + k0 + kc0], true);
            cp16(bBlo + sb + st_off1, &Blo[(size_t)r1 * K + k0 + kc0], true);
        }
        cp_commit();
        cp_wait1();
        __syncthreads();

        const uint32_t sb = (uint32_t)(t & 1) * STAGE_BYTES;

        #pragma unroll
        for (int kk = 0; kk < 32; kk += 16) {
            unsigned bh[4][2], bl[4][2];
            #pragma unroll
            for (int pair = 0; pair < 2; pair++) {
                const uint32_t ad = sb + offB + (uint32_t)(pair * 16 * SPAD + kk) * 2;
                ldsm4(bBhi + ad, bh[pair * 2][0], bh[pair * 2][1],
                      bh[pair * 2 + 1][0], bh[pair * 2 + 1][1]);
                ldsm4(bBlo + ad, bl[pair * 2][0], bl[pair * 2][1],
                      bl[pair * 2 + 1][0], bl[pair * 2 + 1][1]);
            }
            #pragma unroll
            for (int mt = 0; mt < 4; mt++) {
                const uint32_t ad = sb + offA + (uint32_t)(mt * 16 * SPAD + kk) * 2;
                unsigned a0, a1, a2, a3, l0, l1, l2, l3;
                ldsm4(bAhi + ad, a0, a1, a2, a3);
                ldsm4(bAlo + ad, l0, l1, l2, l3);
                #pragma unroll
                for (int nt = 0; nt < 4; nt++) {
                    mma_bf16(acc[mt][nt][0], acc[mt][nt][1], acc[mt][nt][2], acc[mt][nt][3],
                             a0, a1, a2, a3, bh[nt][0], bh[nt][1]);
                    mma_bf16(acc[mt][nt][0], acc[mt][nt][1], acc[mt][nt][2], acc[mt][nt][3],
                             a0, a1, a2, a3, bl[nt][0], bl[nt][1]);
                    mma_bf16(acc[mt][nt][0], acc[mt][nt][1], acc[mt][nt][2], acc[mt][nt][3],
                             l0, l1, l2, l3, bh[nt][0], bh[nt][1]);
                }
            }
        }
        __syncthreads();
    }

    const int g = lane >> 2;
    const int tg = lane & 3;
    #pragma unroll
    for (int mt = 0; mt < 4; mt++) {
        #pragma unroll
        for (int nt = 0; nt < 4; nt++) {
            int r = block_row + warpM * 64 + mt * 16 + g;
            int c = warpN * 32 + nt * 8 + tg * 2;
            if (r < M) {
                float2 v0m = make_float2(acc[mt][nt][0], acc[mt][nt][1]);
                *(float2*)&Y[(size_t)r * HDIM + c] = v0m;
            }
            if (r + 8 < M) {
                float2 v1m = make_float2(acc[mt][nt][2], acc[mt][nt][3]);
                *(float2*)&Y[(size_t)(r + 8) * HDIM + c] = v1m;
            }
        }
    }
}

// ---------------- aggregation (unroll-4 gather) ----------------
__global__ __launch_bounds__(256) void aggregate_kernel(
    const float* __restrict__ y,
    const int* __restrict__ rowp, const int* __restrict__ col,
    const float* __restrict__ nd, const float* __restrict__ ns,
    const float* __restrict__ bias,
    float* __restrict__ out_f32,
    __nv_bfloat16* __restrict__ out_hi, __nv_bfloat16* __restrict__ out_lo,
    int n, int mode) {
    int warp = (blockIdx.x * blockDim.x + threadIdx.x) >> 5;
    int lane = threadIdx.x & 31;
    if (warp >= n) return;

    float4 acc = *((const float4*)(y + (size_t)warp * HDIM) + lane);  // self loop

    const int s = __ldg(&rowp[warp]);
    const int e = __ldg(&rowp[warp + 1]);
    int i = s;
    for (; i + 4 <= e; i += 4) {
        int nb0 = __ldg(&col[i]);
        int nb1 = __ldg(&col[i + 1]);
        int nb2 = __ldg(&col[i + 2]);
        int nb3 = __ldg(&col[i + 3]);
        float4 v0 = *((const float4*)(y + (size_t)nb0 * HDIM) + lane);
        float4 v1 = *((const float4*)(y + (size_t)nb1 * HDIM) + lane);
        float4 v2 = *((const float4*)(y + (size_t)nb2 * HDIM) + lane);
        float4 v3 = *((const float4*)(y + (size_t)nb3 * HDIM) + lane);
        acc.x += (v0.x + v1.x) + (v2.x + v3.x);
        acc.y += (v0.y + v1.y) + (v2.y + v3.y);
        acc.z += (v0.z + v1.z) + (v2.z + v3.z);
        acc.w += (v0.w + v1.w) + (v2.w + v3.w);
    }
    for (; i < e; i++) {
        int nb = __ldg(&col[i]);
        float4 v = *((const float4*)(y + (size_t)nb * HDIM) + lane);
        acc.x += v.x; acc.y += v.y; acc.z += v.z; acc.w += v.w;
    }

    float sc = nd[warp];
    float4 b = ((const float4*)bias)[lane];
    float4 r;
    r.x = fmaf(acc.x, sc, b.x);
    r.y = fmaf(acc.y, sc, b.y);
    r.z = fmaf(acc.z, sc, b.z);
    r.w = fmaf(acc.w, sc, b.w);
    if (mode) {
        r.x = fmaxf(r.x, 0.f); r.y = fmaxf(r.y, 0.f);
        r.z = fmaxf(r.z, 0.f); r.w = fmaxf(r.w, 0.f);
        float nsv = ns[warp];
        union { ushort4 u; __nv_bfloat16 bb[4]; } H, L;
        split_bf16(r.x * nsv, H.bb[0], L.bb[0]);
        split_bf16(r.y * nsv, H.bb[1], L.bb[1]);
        split_bf16(r.z * nsv, H.bb[2], L.bb[2]);
        split_bf16(r.w * nsv, H.bb[3], L.bb[3]);
        *(ushort4*)&out_hi[(size_t)warp * HDIM + lane * 4] = H.u;
        *(ushort4*)&out_lo[(size_t)warp * HDIM + lane * 4] = L.u;
    } else {
        ((float4*)(out_f32 + (size_t)warp * HDIM))[lane] = r;
    }
}

// ---------------- host orchestration ----------------
static inline int cdiv(int a, int b) { return (a + b - 1) / b; }

extern "C" void kernel_launch(void* const* d_in, const int* in_sizes, int n_in,
                              void* d_out, int out_size) {
    const float* feat_a = (const float*)d_in[0];
    const float* feat_b = (const float*)d_in[1];
    const int* src_a = (const int*)d_in[2];
    const int* dst_a = (const int*)d_in[3];
    const int* src_b = (const int*)d_in[4];
    const int* dst_b = (const int*)d_in[5];
    const float* Wa0 = (const float*)d_in[6];
    const float* ba0 = (const float*)d_in[7];
    const float* Wa1 = (const float*)d_in[8];
    const float* ba1 = (const float*)d_in[9];
    const float* Wb0 = (const float*)d_in[10];
    const float* bb0 = (const float*)d_in[11];
    const float* Wb1 = (const float*)d_in[12];
    const float* bb1 = (const float*)d_in[13];

    const int H = in_sizes[7];
    const int DA = in_sizes[6] / H;
    const int NA = in_sizes[0] / DA;
    const int EA = in_sizes[2];
    const int DB = in_sizes[10] / H;
    const int NB = in_sizes[1] / DB;
    const int EB = in_sizes[4];

    float* out = (float*)d_out;
    float* out_a = out;
    float* out_b = out + (size_t)NA * HDIM;

    __nv_bfloat16 *XhiA, *XloA, *XhiB, *XloB;
    __nv_bfloat16 *WhiA0, *WloA0, *WhiA1, *WloA1, *WhiB0, *WloB0, *WhiB1, *WloB1;
    float *YA, *YB, *nsA, *ndA, *nsB, *ndB;
    int *cntOutA, *cntInA, *fillA, *rowpA, *colA;
    int *cntOutB, *cntInB, *fillB, *rowpB, *colB;
    int *bsumA, *bsumB;
    cudaGetSymbolAddress((void**)&XhiA, g_XhiA);
    cudaGetSymbolAddress((void**)&XloA, g_XloA);
    cudaGetSymbolAddress((void**)&YA, g_YA);
    cudaGetSymbolAddress((void**)&XhiB, g_XhiB);
    cudaGetSymbolAddress((void**)&XloB, g_XloB);
    cudaGetSymbolAddress((void**)&YB, g_YB);
    cudaGetSymbolAddress((void**)&WhiA0, g_WhiA0);
    cudaGetSymbolAddress((void**)&WloA0, g_WloA0);
    cudaGetSymbolAddress((void**)&WhiA1, g_WhiA1);
    cudaGetSymbolAddress((void**)&WloA1, g_WloA1);
    cudaGetSymbolAddress((void**)&WhiB0, g_WhiB0);
    cudaGetSymbolAddress((void**)&WloB0, g_WloB0);
    cudaGetSymbolAddress((void**)&WhiB1, g_WhiB1);
    cudaGetSymbolAddress((void**)&WloB1, g_WloB1);
    cudaGetSymbolAddress((void**)&nsA, g_nsA);
    cudaGetSymbolAddress((void**)&ndA, g_ndA);
    cudaGetSymbolAddress((void**)&nsB, g_nsB);
    cudaGetSymbolAddress((void**)&ndB, g_ndB);
    cudaGetSymbolAddress((void**)&cntOutA, g_cntOutA);
    cudaGetSymbolAddress((void**)&cntInA, g_cntInA);
    cudaGetSymbolAddress((void**)&fillA, g_fillA);
    cudaGetSymbolAddress((void**)&rowpA, g_rowpA);
    cudaGetSymbolAddress((void**)&colA, g_colA);
    cudaGetSymbolAddress((void**)&cntOutB, g_cntOutB);
    cudaGetSymbolAddress((void**)&cntInB, g_cntInB);
    cudaGetSymbolAddress((void**)&fillB, g_fillB);
    cudaGetSymbolAddress((void**)&rowpB, g_rowpB);
    cudaGetSymbolAddress((void**)&colB, g_colB);
    cudaGetSymbolAddress((void**)&bsumA, g_bsumA);
    cudaGetSymbolAddress((void**)&bsumB, g_bsumB);

    cudaFuncSetAttribute(gemm_bf16_kernel,
                         cudaFuncAttributeMaxDynamicSharedMemorySize, GEMM_SMEM);

    const int T = 256;
    const int nblkA = cdiv(NA, 1024);
    const int nblkB = cdiv(NB, 1024);
    cudaStream_t s2 = g_si.s2;
    cudaStream_t s3 = g_si.s3;

    // ---- fork s2 immediately: weight conversions depend on nothing ----
    cudaEventRecord(g_si.evFork, 0);
    cudaStreamWaitEvent(s2, g_si.evFork, 0);
    {
        int total = DA * H + H * H + DB * H + H * H;
        convW_all_kernel<<<cdiv(total, T), T, 0, s2>>>(Wa0, Wa1, Wb0, Wb1,
                                                       WhiA0, WloA0, WhiA1, WloA1,
                                                       WhiB0, WloB0, WhiB1, WloB1,
                                                       DA, DB, H);
    }
    cudaEventRecord(g_si.evW, s2);

    // ---- degree prep (legacy stream) ----
    zero_all_kernel<<<cdiv(NA, T), T>>>(cntOutA, cntInA, fillA, NA,
                                        cntOutB, cntInB, fillB, NB);
    count_deg_both_kernel<<<cdiv(EA > EB ? EA : EB, T), T>>>(
        src_a, dst_a, EA, cntOutA, cntInA,
        src_b, dst_b, EB, cntOutB, cntInB);
    norms_both_kernel<<<cdiv(NA > NB ? NA : NB, T), T>>>(
        cntOutA, cntInA, nsA, ndA, NA,
        cntOutB, cntInB, nsB, ndB, NB);

    // ---- fork s3 for CSR build (after norms; needs cntIn) ----
    cudaEventRecord(g_si.evFork, 0);
    cudaStreamWaitEvent(s3, g_si.evFork, 0);
    // s2's B chain also needs ns: it waits on the same event below.
    cudaStreamWaitEvent(s2, g_si.evFork, 0);

    scan1_kernel<<<nblkA + nblkB, 1024, 0, s3>>>(cntInA, rowpA, NA, nblkA,
                                                 cntInB, rowpB, NB, bsumA, bsumB);
    scan2_kernel<<<2, 1024, 0, s3>>>(bsumA, nblkA, bsumB, nblkB);
    scan3_kernel<<<nblkA + nblkB, 1024, 0, s3>>>(rowpA, NA, nblkA, rowpB, NB, bsumA, bsumB);
    csr_fill_both_kernel<<<cdiv(EA > EB ? EA : EB, T), T, 0, s3>>>(
        src_a, dst_a, EA, rowpA, fillA, colA,
        src_b, dst_b, EB, rowpB, fillB, colB);
    cudaEventRecord(g_si.evCSR, s3);

    // ===== stream0: ntype A =====
    {
        int nq = NA * DA / 4;
        int kqshift = (DA == 256) ? 6 : 5;
        convert_feat_kernel<<<cdiv(nq, T), T>>>(feat_a, nsA, XhiA, XloA, nq, kqshift);
    }
    cudaStreamWaitEvent((cudaStream_t)0, g_si.evW, 0);
    gemm_bf16_kernel<<<cdiv(NA, 128), 256, GEMM_SMEM>>>(XhiA, XloA, WhiA0, WloA0, YA, NA, DA);
    cudaStreamWaitEvent((cudaStream_t)0, g_si.evCSR, 0);
    aggregate_kernel<<<cdiv(NA * 32, 256), 256>>>(YA, rowpA, colA, ndA, nsA, ba0,
                                                  nullptr, XhiA, XloA, NA, 1);
    gemm_bf16_kernel<<<cdiv(NA, 128), 256, GEMM_SMEM>>>(XhiA, XloA, WhiA1, WloA1, YA, NA, H);
    aggregate_kernel<<<cdiv(NA * 32, 256), 256>>>(YA, rowpA, colA, ndA, nsA, ba1,
                                                  out_a, nullptr, nullptr, NA, 0);

    // ===== s2: ntype B (convW already in-stream; ns via evFork wait above) =====
    {
        int nq = NB * DB / 4;
        int kqshift = (DB == 256) ? 6 : 5;
        convert_feat_kernel<<<cdiv(nq, T), T, 0, s2>>>(feat_b, nsB, XhiB, XloB, nq, kqshift);
    }
    gemm_bf16_kernel<<<cdiv(NB, 128), 256, GEMM_SMEM, s2>>>(XhiB, XloB, WhiB0, WloB0, YB, NB, DB);
    cudaStreamWaitEvent(s2, g_si.evCSR, 0);
    aggregate_kernel<<<cdiv(NB * 32, 256), 256, 0, s2>>>(YB, rowpB, colB, ndB, nsB, bb0,
                                                         nullptr, XhiB, XloB, NB, 1);
    gemm_bf16_kernel<<<cdiv(NB, 128), 256, GEMM_SMEM, s2>>>(XhiB, XloB, WhiB1, WloB1, YB, NB, H);
    aggregate_kernel<<<cdiv(NB * 32, 256), 256, 0, s2>>>(YB, rowpB, colB, ndB, nsB, bb1,
                                                         out_b, nullptr, nullptr, NB, 0);

    // ---- join back to legacy stream ----
    cudaEventRecord(g_si.evJoin, s2);
    cudaStreamWaitEvent((cudaStream_t)0, g_si.evJoin, 0);

    (void)n_in; (void)out_size;
}